// round 12
// baseline (speedup 1.0000x reference)
#include <cuda_runtime.h>
#include <cuda_bf16.h>
#include <math.h>
#include <stdint.h>

#define Bq   4
#define Cc   128
#define Hh   240
#define Ww   240
#define NK   400
#define CELL 12
#define GHW  20
#define PATCH 144
#define HWIMG (Hh*Ww)     /* 57600 */
#define MT   450          /* m-tiles of 128 */
#define EPSV 1e-6f

// ---------------- scratch (static device globals; no allocation) ----------------
__device__ float g_ps[Bq*NK*2];
__device__ float g_pd[Bq*NK*2];
__device__ float g_ds[Bq*NK*Cc];
__device__ __nv_bfloat16 g_ds_bf16[Bq*NK*Cc];
__device__ __nv_bfloat16 g_d2n[(size_t)Bq*Cc*HWIMG];   // 59 MB normalized desc2
__device__ float g_ss[Bq*NK];
__device__ float g_w[Bq*NK];
__device__ float4 g_part[(size_t)Bq*NK*MT];   // 11.5 MB, [b][row][mt]
__device__ unsigned int g_cnt;                // zero-init; reset by last block each run

// ================= helpers =================
__device__ __forceinline__ uint32_t smem_u32(const void* p) {
    uint32_t a;
    asm("{ .reg .u64 t; cvta.to.shared.u64 t, %1; cvt.u32.u64 %0, t; }" : "=r"(a) : "l"(p));
    return a;
}
__device__ __forceinline__ void ldmat4(uint32_t* r, uint32_t addr) {
    asm volatile("ldmatrix.sync.aligned.m8n8.x4.shared.b16 {%0,%1,%2,%3}, [%4];"
        : "=r"(r[0]), "=r"(r[1]), "=r"(r[2]), "=r"(r[3]) : "r"(addr));
}
__device__ __forceinline__ void ldmat4t(uint32_t* r, uint32_t addr) {
    asm volatile("ldmatrix.sync.aligned.m8n8.x4.trans.shared.b16 {%0,%1,%2,%3}, [%4];"
        : "=r"(r[0]), "=r"(r[1]), "=r"(r[2]), "=r"(r[3]) : "r"(addr));
}
__device__ __forceinline__ void mma16816(float* c, const uint32_t* a, const uint32_t* b) {
    asm volatile("mma.sync.aligned.m16n8k16.row.col.f32.bf16.bf16.f32 "
        "{%0,%1,%2,%3}, {%4,%5,%6,%7}, {%8,%9}, {%0,%1,%2,%3};"
        : "+f"(c[0]), "+f"(c[1]), "+f"(c[2]), "+f"(c[3])
        : "r"(a[0]), "r"(a[1]), "r"(a[2]), "r"(a[3]), "r"(b[0]), "r"(b[1]));
}
#define CP16(dst, src)  asm volatile("cp.async.cg.shared.global [%0], [%1], 16;" :: "r"(dst), "l"(src))
#define CP_COMMIT()     asm volatile("cp.async.commit_group;")
#define CP_WAIT(n)      asm volatile("cp.async.wait_group %0;" :: "n"(n))

// swizzled byte offset within a [rows x 128 bf16] tile (row pitch 256B)
#define SWZ(row, c16) ((uint32_t)(row)*256u + (uint32_t)(((c16) ^ ((row)&7)) << 4))

// block reductions over 128 threads (broadcast to all)
__device__ __forceinline__ float block_sum_128(float v, float* red4)
{
    #pragma unroll
    for (int o = 16; o > 0; o >>= 1) v += __shfl_xor_sync(0xffffffffu, v, o);
    int w = threadIdx.x >> 5;
    __syncthreads();
    if ((threadIdx.x & 31) == 0) red4[w] = v;
    __syncthreads();
    return red4[0] + red4[1] + red4[2] + red4[3];
}
__device__ __forceinline__ float block_max_128(float v, float* red4)
{
    #pragma unroll
    for (int o = 16; o > 0; o >>= 1) v = fmaxf(v, __shfl_xor_sync(0xffffffffu, v, o));
    int w = threadIdx.x >> 5;
    __syncthreads();
    if ((threadIdx.x & 31) == 0) red4[w] = v;
    __syncthreads();
    return fmaxf(fmaxf(red4[0], red4[1]), fmaxf(red4[2], red4[3]));
}
// fused 3-value reduction over 256 threads (8 warps), ONE barrier
__device__ __forceinline__ void block_sum3_256(float& a, float& b, float& c, float* red24)
{
    #pragma unroll
    for (int o = 16; o > 0; o >>= 1) {
        a += __shfl_xor_sync(0xffffffffu, a, o);
        b += __shfl_xor_sync(0xffffffffu, b, o);
        c += __shfl_xor_sync(0xffffffffu, c, o);
    }
    int w = threadIdx.x >> 5;
    if ((threadIdx.x & 31) == 0) { red24[w*3] = a; red24[w*3+1] = b; red24[w*3+2] = c; }
    __syncthreads();
    a = red24[0]; b = red24[1]; c = red24[2];
    #pragma unroll
    for (int i = 1; i < 8; i++) { a += red24[i*3]; b += red24[i*3+1]; c += red24[i*3+2]; }
}

// bilinear helpers ---------------------------------------------------------
__device__ __forceinline__ void bilin_setup(float px, float py,
    int& x0, int& y0, int& x1, int& y1, float& wx, float& wy)
{
    float x = fminf(fmaxf(px, 0.f), (float)(Ww-1));
    float y = fminf(fmaxf(py, 0.f), (float)(Hh-1));
    float x0f = floorf(x), y0f = floorf(y);
    wx = x - x0f; wy = y - y0f;
    x0 = (int)x0f; y0 = (int)y0f;
    x1 = min(x0 + 1, Ww-1);
    y1 = min(y0 + 1, Hh-1);
}
__device__ __forceinline__ float bilin_fetch(const float* __restrict__ base,
    int x0, int y0, int x1, int y1, float wx, float wy)
{
    float v00 = base[y0*Ww + x0];
    float v01 = base[y0*Ww + x1];
    float v10 = base[y1*Ww + x0];
    float v11 = base[y1*Ww + x1];
    return v00*(1.f-wx)*(1.f-wy) + v01*wx*(1.f-wy) + v10*(1.f-wx)*wy + v11*wx*wy;
}

// ---------------- 1) fused prep: keypoints+ds OR desc2-normalize (role by blockIdx) ----
#define KPB   (NK*Bq)            /* 1600 kpds blocks */
#define D2NB  ((Bq*Cc*Hh)/4)     /* 30720 d2n blocks (4 warps = 4 rows each) */

__global__ void prep_kernel(const float* __restrict__ loc,
                            const float* __restrict__ desc1,
                            const float* __restrict__ sc1,
                            const float* __restrict__ desc2)
{
    int blk = blockIdx.x;
    int t = threadIdx.x;   // 128

    if (blk >= KPB) {
        // ---- d2n role: one warp per (b,c,y) row ----
        int gwarp = (blk - KPB)*4 + (t >> 5);
        int lane  = t & 31;
        const float* rowp = desc2 + (size_t)gwarp * Ww;
        float v[8];
        float s = 0.f;
        #pragma unroll
        for (int k = 0; k < 8; k++) {
            int x = lane + k*32;
            v[k] = (x < Ww) ? rowp[x] : 0.f;
            s += v[k]*v[k];
        }
        #pragma unroll
        for (int o = 16; o > 0; o >>= 1) s += __shfl_xor_sync(0xffffffffu, s, o);
        float inv = 1.f / (sqrtf(s) + EPSV);
        __nv_bfloat16* outp = g_d2n + (size_t)gwarp * Ww;
        #pragma unroll
        for (int k = 0; k < 8; k++) {
            int x = lane + k*32;
            if (x < Ww) outp[x] = __float2bfloat16(v[k] * inv);
        }
        return;
    }

    // ---- kpds role ----
    int n = blk % NK, b = blk / NK;
    int i = n / GHW, j = n % GHW;
    __shared__ float red4[4];

    int r0 = t / CELL, c0 = t % CELL;
    float v0 = loc[((size_t)b*Hh + i*CELL + r0)*Ww + j*CELL + c0];
    float v1 = -1e30f; int r1 = 0, c1 = 0;
    if (t < PATCH - 128) {
        int e = t + 128;
        r1 = e / CELL; c1 = e % CELL;
        v1 = loc[((size_t)b*Hh + i*CELL + r1)*Ww + j*CELL + c1];
    }
    float mx = block_max_128(fmaxf(v0, v1), red4);
    float p0 = __expf(v0 - mx);
    float p1 = (t < PATCH - 128) ? __expf(v1 - mx) : 0.f;

    float s  = block_sum_128(p0 + p1, red4);
    float sx = block_sum_128(p0*(float)c0 + p1*(float)c1, red4);
    float sy = block_sum_128(p0*(float)r0 + p1*(float)r1, red4);

    float psx = sx / s + (float)(i * CELL);   // reference quirk: x offset from ROW block
    float psy = sy / s + (float)(j * CELL);
    if (t == 0) {
        g_ps[(b*NK + n)*2 + 0] = psx;
        g_ps[(b*NK + n)*2 + 1] = psy;
    }

    int c = t;
    int x0,y0,x1,y1; float wx,wy;
    bilin_setup(psx, psy, x0,y0,x1,y1, wx,wy);

    const float* base = desc1 + ((size_t)b*Cc + c) * HWIMG;
    float v = bilin_fetch(base, x0,y0,x1,y1, wx,wy);

    float tot = block_sum_128(v*v, red4);
    float nrm = sqrtf(tot) + EPSV;
    float dsv = v / nrm;
    g_ds[((size_t)b*NK + n)*Cc + c] = dsv;
    g_ds_bf16[((size_t)b*NK + n)*Cc + c] = __float2bfloat16(dsv);

    if (c == 0) {
        const float* sb = sc1 + (size_t)b*HWIMG;
        g_ss[b*NK + n] = bilin_fetch(sb, x0,y0,x1,y1, wx,wy);
    }
}

// ---------------- 2) fused HMMA GEMM + partial softmax ----------
// grid (MT, Bq), 256 threads (8 warps, 4x2; warp tile 32n x 64m).
// Tail A-tile gets its own buffer (prefetched upfront); only A2 refills mid-loop.
#define SM_A0    0
#define SM_A1    32768
#define SM_BS    65536
#define SM_AT    98304                 /* tail 16x128 bf16 = 4096 B */
#define SM_STAT  102400                /* float[3][128] = 1536 B */
#define SM_TOTAL 103936

__global__ void __launch_bounds__(256, 2)
mma_kernel()
{
    extern __shared__ char smem[];
    uint32_t sbase = smem_u32(smem);
    float* statS = (float*)(smem + SM_STAT);
    float* statY = statS + 128;
    float* statX = statS + 256;
    int tid  = threadIdx.x;
    int lane = tid & 31;
    int wid  = tid >> 5;
    int wr   = wid >> 1;        // warp row 0..3
    int wc   = wid & 1;         // warp col 0..1
    int mt   = blockIdx.x, b = blockIdx.y;
    int m0   = mt * 128;

    const char* abase = (const char*)(g_ds_bf16 + (size_t)b*NK*Cc);
    const char* bbase = (const char*)(g_d2n + (size_t)b*Cc*HWIMG);

    // prefetch B (g0)
    #pragma unroll
    for (int k = 0; k < 8; k++) {
        int gi  = tid + k*256;
        int c   = gi >> 4;
        int c16 = gi & 15;
        CP16(sbase + SM_BS + SWZ(c, c16),
             bbase + ((size_t)c*HWIMG + m0)*2 + c16*16);
    }
    CP_COMMIT();
    // prefetch A0 (g1), A1 (g2)
    #pragma unroll
    for (int at = 0; at < 2; at++) {
        const char* asrc = abase + (size_t)at*128*256;
        uint32_t dbase = sbase + (at ? SM_A1 : SM_A0);
        #pragma unroll
        for (int k = 0; k < 8; k++) {
            int gi  = tid + k*256;
            int row = gi >> 4;
            int c16 = gi & 15;
            CP16(dbase + SWZ(row, c16), asrc + (size_t)gi*16);
        }
        CP_COMMIT();
    }
    // prefetch tail rows 384..399 (g3) into its own buffer
    {
        const char* asrc = abase + (size_t)384*256;
        int row = tid >> 4;
        int c16 = tid & 15;
        CP16(sbase + SM_AT + SWZ(row, c16), asrc + (size_t)tid*16);
        CP_COMMIT();
    }

    uint32_t bs_base = sbase + SM_BS;

    int arow  = wr*32 + (lane & 15);
    int ako   = lane >> 4;
    int bcrow = (lane & 7) + (((lane >> 3) & 1) << 3);
    int bmsub = (lane >> 4) << 3;

    #pragma unroll
    for (int at = 0; at < 3; at++) {
        if (at == 0)      { CP_WAIT(2); }   // B + A0 done (A1, tail may pend)
        else if (at == 1) { CP_WAIT(2); }   // A1 done (tail, A2 may pend)
        else              { CP_WAIT(0); }   // everything done (A2)
        __syncthreads();   // A(at) ready; also fences stat reuse from prev tile

        uint32_t as_base = sbase + ((at & 1) ? SM_A1 : SM_A0);

        float acc[2][8][4];
        #pragma unroll
        for (int mi = 0; mi < 2; mi++)
            #pragma unroll
            for (int nf = 0; nf < 8; nf++)
                #pragma unroll
                for (int q = 0; q < 4; q++) acc[mi][nf][q] = 0.f;

        #pragma unroll
        for (int ks = 0; ks < 8; ks++) {
            uint32_t a0[4], a1[4];
            ldmat4(a0, as_base + SWZ(arow,      ks*2 + ako));
            ldmat4(a1, as_base + SWZ(arow + 16, ks*2 + ako));
            uint32_t bfr[4][4];
            #pragma unroll
            for (int np = 0; np < 4; np++)
                ldmat4t(bfr[np], bs_base + SWZ(ks*16 + bcrow, (wc*64 + np*16 + bmsub) >> 3));
            #pragma unroll
            for (int nf = 0; nf < 8; nf++) {
                uint32_t bb[2];
                bb[0] = bfr[nf >> 1][(nf & 1)*2 + 0];
                bb[1] = bfr[nf >> 1][(nf & 1)*2 + 1];
                mma16816(acc[0][nf], a0, bb);
                mma16816(acc[1][nf], a1, bb);
            }
        }

        // epilogue (registers only) BEFORE barrier: overlaps other warps' MMA
        float st[2][2][3];
        #pragma unroll
        for (int mi = 0; mi < 2; mi++) {
            float s0=0.f, sy0=0.f, sx0=0.f, s1=0.f, sy1=0.f, sx1=0.f;
            #pragma unroll
            for (int nf = 0; nf < 8; nf++) {
                int col = wc*64 + nf*8 + (lane & 3)*2;
                int m   = m0 + col;
                int ya  = m / Ww;        float yaf = (float)ya, xaf = (float)(m - ya*Ww);
                int mb2 = m + 1;
                int yb  = mb2 / Ww;      float ybf = (float)yb, xbf = (float)(mb2 - yb*Ww);
                float e;
                e = __expf(acc[mi][nf][0]); s0 += e; sy0 += e*yaf; sx0 += e*xaf;
                e = __expf(acc[mi][nf][1]); s0 += e; sy0 += e*ybf; sx0 += e*xbf;
                e = __expf(acc[mi][nf][2]); s1 += e; sy1 += e*yaf; sx1 += e*xaf;
                e = __expf(acc[mi][nf][3]); s1 += e; sy1 += e*ybf; sx1 += e*xbf;
            }
            #pragma unroll
            for (int o = 1; o <= 2; o <<= 1) {
                s0  += __shfl_xor_sync(0xffffffffu, s0,  o);
                sy0 += __shfl_xor_sync(0xffffffffu, sy0, o);
                sx0 += __shfl_xor_sync(0xffffffffu, sx0, o);
                s1  += __shfl_xor_sync(0xffffffffu, s1,  o);
                sy1 += __shfl_xor_sync(0xffffffffu, sy1, o);
                sx1 += __shfl_xor_sync(0xffffffffu, sx1, o);
            }
            st[mi][0][0]=s0; st[mi][0][1]=sy0; st[mi][0][2]=sx0;
            st[mi][1][0]=s1; st[mi][1][1]=sy1; st[mi][1][2]=sx1;
        }
        if (wc == 1 && (lane & 3) == 0) {
            #pragma unroll
            for (int mi = 0; mi < 2; mi++) {
                int rl = wr*32 + mi*16 + (lane >> 2);
                statS[rl]   = st[mi][0][0]; statY[rl]   = st[mi][0][1]; statX[rl]   = st[mi][0][2];
                statS[rl+8] = st[mi][1][0]; statY[rl+8] = st[mi][1][1]; statX[rl+8] = st[mi][1][2];
            }
        }
        __syncthreads();   // A-buf reads complete + stat visible

        // refill A2 -> buf0 (only needed after tile 0); overlaps tile 1 fully
        if (at == 0) {
            const char* asrc = abase + (size_t)2*128*256;
            #pragma unroll
            for (int k = 0; k < 8; k++) {
                int gi  = tid + k*256;
                int row = gi >> 4;
                int c16 = gi & 15;
                CP16(sbase + SM_A0 + SWZ(row, c16), asrc + (size_t)gi*16);
            }
            CP_COMMIT();
        }

        if (wc == 0 && (lane & 3) == 0) {
            #pragma unroll
            for (int mi = 0; mi < 2; mi++) {
                int rl = wr*32 + mi*16 + (lane >> 2);
                g_part[((size_t)b*NK + at*128 + rl)*MT + mt] =
                    make_float4(st[mi][0][0]+statS[rl], st[mi][0][1]+statY[rl], st[mi][0][2]+statX[rl], 0.f);
                g_part[((size_t)b*NK + at*128 + rl + 8)*MT + mt] =
                    make_float4(st[mi][1][0]+statS[rl+8], st[mi][1][1]+statY[rl+8], st[mi][1][2]+statX[rl+8], 0.f);
            }
        }
    }

    // ---- tail tile: rows 384..399 (16 rows), warps 0,1 only ----
    __syncthreads();   // fence stat reuse from tile 2
    float tst[2][3];
    if (wid < 2) {
        uint32_t as_base = sbase + SM_AT;
        float acc[8][4];
        #pragma unroll
        for (int nf = 0; nf < 8; nf++)
            #pragma unroll
            for (int q = 0; q < 4; q++) acc[nf][q] = 0.f;

        int arow_t = lane & 15;
        #pragma unroll
        for (int ks = 0; ks < 8; ks++) {
            uint32_t a[4];
            ldmat4(a, as_base + SWZ(arow_t, ks*2 + ako));
            uint32_t bfr[4][4];
            #pragma unroll
            for (int np = 0; np < 4; np++)
                ldmat4t(bfr[np], bs_base + SWZ(ks*16 + bcrow, (wc*64 + np*16 + bmsub) >> 3));
            #pragma unroll
            for (int nf = 0; nf < 8; nf++) {
                uint32_t bb[2];
                bb[0] = bfr[nf >> 1][(nf & 1)*2 + 0];
                bb[1] = bfr[nf >> 1][(nf & 1)*2 + 1];
                mma16816(acc[nf], a, bb);
            }
        }

        float s0=0.f, sy0=0.f, sx0=0.f, s1=0.f, sy1=0.f, sx1=0.f;
        #pragma unroll
        for (int nf = 0; nf < 8; nf++) {
            int col = wc*64 + nf*8 + (lane & 3)*2;
            int m   = m0 + col;
            int ya  = m / Ww;        float yaf = (float)ya, xaf = (float)(m - ya*Ww);
            int mb2 = m + 1;
            int yb  = mb2 / Ww;      float ybf = (float)yb, xbf = (float)(mb2 - yb*Ww);
            float e;
            e = __expf(acc[nf][0]); s0 += e; sy0 += e*yaf; sx0 += e*xaf;
            e = __expf(acc[nf][1]); s0 += e; sy0 += e*ybf; sx0 += e*xbf;
            e = __expf(acc[nf][2]); s1 += e; sy1 += e*yaf; sx1 += e*xaf;
            e = __expf(acc[nf][3]); s1 += e; sy1 += e*ybf; sx1 += e*xbf;
        }
        #pragma unroll
        for (int o = 1; o <= 2; o <<= 1) {
            s0  += __shfl_xor_sync(0xffffffffu, s0,  o);
            sy0 += __shfl_xor_sync(0xffffffffu, sy0, o);
            sx0 += __shfl_xor_sync(0xffffffffu, sx0, o);
            s1  += __shfl_xor_sync(0xffffffffu, s1,  o);
            sy1 += __shfl_xor_sync(0xffffffffu, sy1, o);
            sx1 += __shfl_xor_sync(0xffffffffu, sx1, o);
        }
        tst[0][0]=s0; tst[0][1]=sy0; tst[0][2]=sx0;
        tst[1][0]=s1; tst[1][1]=sy1; tst[1][2]=sx1;
        if (wid == 1 && (lane & 3) == 0) {
            int rl = lane >> 2;
            statS[rl]   = s0; statY[rl]   = sy0; statX[rl]   = sx0;
            statS[rl+8] = s1; statY[rl+8] = sy1; statX[rl+8] = sx1;
        }
    }
    __syncthreads();
    if (wid == 0 && (lane & 3) == 0) {
        int rl = lane >> 2;
        g_part[((size_t)b*NK + 384 + rl)*MT + mt] =
            make_float4(tst[0][0]+statS[rl], tst[0][1]+statY[rl], tst[0][2]+statX[rl], 0.f);
        g_part[((size_t)b*NK + 384 + rl + 8)*MT + mt] =
            make_float4(tst[1][0]+statS[rl+8], tst[1][1]+statY[rl+8], tst[1][2]+statX[rl+8], 0.f);
    }
}

// ---------------- 3) fused reduce -> pd -> dd + w_ -> (last block) pose + loss ----------
__global__ void reduce_dd_kernel(const float* __restrict__ desc2, const float* __restrict__ sc2,
                                 const float* __restrict__ pos_trans, float* __restrict__ out)
{
    int n = blockIdx.x, b = blockIdx.y;
    int t = threadIdx.x;  // 256
    __shared__ float red24[24];
    __shared__ float pd_s[2];
    __shared__ unsigned int lastFlag;

    // --- reduce partials (coalesced, fused 3-value reduction) ---
    {
        const float4* src = g_part + ((size_t)b*NK + n)*MT;
        float4 p0 = (t       < MT) ? src[t]       : make_float4(0,0,0,0);
        float4 p1 = (t + 256 < MT) ? src[t + 256] : make_float4(0,0,0,0);
        float s  = p0.x + p1.x;
        float sy = p0.y + p1.y;
        float sx = p0.z + p1.z;
        block_sum3_256(s, sy, sx, red24);
        if (t == 0) {
            float v0 = sy / s, v1 = sx / s;
            pd_s[0] = v0; pd_s[1] = v1;
            g_pd[(b*NK+n)*2 + 0] = v0;
            g_pd[(b*NK+n)*2 + 1] = v1;
        }
        __syncthreads();
    }

    // --- dd: bilinear(desc2, pd), normalize, dot with ds; sd; w_ ---
    float px = pd_s[0];   // pd[...,0] consumed as "x" (reference quirk)
    float py = pd_s[1];
    int x0,y0,x1,y1; float wx,wy;
    bilin_setup(px, py, x0,y0,x1,y1, wx,wy);

    float v = 0.f, dsv = 0.f;
    if (t < Cc) {
        const float* base = desc2 + ((size_t)b*Cc + t) * HWIMG;
        v = bilin_fetch(base, x0,y0,x1,y1, wx,wy);
        dsv = g_ds[((size_t)b*NK + n)*Cc + t];
    }
    float ssq = v*v, sdot = dsv*v, dummy = 0.f;
    __syncthreads();   // red24 reuse safety
    block_sum3_256(ssq, sdot, dummy, red24);

    if (t == 0) {
        float dot = sdot / (sqrtf(ssq) + EPSV);
        const float* sb = sc2 + (size_t)b*HWIMG;
        float sd = bilin_fetch(sb, x0,y0,x1,y1, wx,wy);
        g_w[b*NK + n] = (dot + 1.f) * (g_ss[b*NK + n] * sd) * 0.5f;
        __threadfence();
        unsigned int vcnt = atomicAdd(&g_cnt, 1u);
        lastFlag = (vcnt == (unsigned int)(NK*Bq - 1)) ? 1u : 0u;
    }
    __syncthreads();
    if (!lastFlag) return;

    // ===== last block: pose estimation + loss + mean (all g_w/g_pd now visible) =====
    if (t == 0) g_cnt = 0;    // reset for next graph replay

    __shared__ float sp[8][9];
    __shared__ float losses[Bq];
    {
        int wid = t >> 5, lane = t & 31;
        int bb = wid & 3;          // batch
        int half = wid >> 2;       // two warps per batch
        const float RES = 0.25f;
        const float OX = (Ww - 1) * 0.5f;
        const float OY = (Hh - 1) * 0.5f;

        float W=0, Ax=0, Ay=0, Bx=0, By=0, M00=0, M01=0, M10=0, M11=0;
        for (int k = lane + half*32; k < NK; k += 64) {
            float wv = g_w[bb*NK + k];
            float psx = g_ps[(bb*NK+k)*2+0], psy = g_ps[(bb*NK+k)*2+1];
            float pdx = g_pd[(bb*NK+k)*2+0], pdy = g_pd[(bb*NK+k)*2+1];
            float qsx = (psx - OX) * RES, qsy = (OY - psy) * RES;
            float qdx = (pdx - OX) * RES, qdy = (OY - pdy) * RES;
            W  += wv;
            Ax += wv*qsx; Ay += wv*qsy;
            Bx += wv*qdx; By += wv*qdy;
            M00 += wv*qsx*qdx; M01 += wv*qsx*qdy;
            M10 += wv*qsy*qdx; M11 += wv*qsy*qdy;
        }
        #pragma unroll
        for (int o = 16; o > 0; o >>= 1) {
            W   += __shfl_xor_sync(0xffffffffu, W,   o);
            Ax  += __shfl_xor_sync(0xffffffffu, Ax,  o);
            Ay  += __shfl_xor_sync(0xffffffffu, Ay,  o);
            Bx  += __shfl_xor_sync(0xffffffffu, Bx,  o);
            By  += __shfl_xor_sync(0xffffffffu, By,  o);
            M00 += __shfl_xor_sync(0xffffffffu, M00, o);
            M01 += __shfl_xor_sync(0xffffffffu, M01, o);
            M10 += __shfl_xor_sync(0xffffffffu, M10, o);
            M11 += __shfl_xor_sync(0xffffffffu, M11, o);
        }
        if (lane == 0) {
            sp[wid][0]=W;  sp[wid][1]=Ax;  sp[wid][2]=Ay;
            sp[wid][3]=Bx; sp[wid][4]=By;  sp[wid][5]=M00;
            sp[wid][6]=M01; sp[wid][7]=M10; sp[wid][8]=M11;
        }
        __syncthreads();
        if (t < Bq) {
            int bb2 = t;
            float Wc   = sp[bb2][0] + sp[bb2+4][0];
            float Axc  = sp[bb2][1] + sp[bb2+4][1];
            float Ayc  = sp[bb2][2] + sp[bb2+4][2];
            float Bxc  = sp[bb2][3] + sp[bb2+4][3];
            float Byc  = sp[bb2][4] + sp[bb2+4][4];
            float m00  = sp[bb2][5] + sp[bb2+4][5];
            float m01  = sp[bb2][6] + sp[bb2+4][6];
            float m10  = sp[bb2][7] + sp[bb2+4][7];
            float m11  = sp[bb2][8] + sp[bb2+4][8];
            float wsum = Wc + EPSV;
            float qax = Axc / wsum, qay = Ayc / wsum;
            float qbx = Bxc / wsum, qby = Byc / wsum;
            float S00 = m00 - qax*Bxc - Axc*qbx + Wc*qax*qbx;
            float S01 = m01 - qax*Byc - Axc*qby + Wc*qax*qby;
            float S10 = m10 - qay*Bxc - Ayc*qbx + Wc*qay*qbx;
            float S11 = m11 - qay*Byc - Ayc*qby + Wc*qay*qby;
            float cc = S00 + S11;
            float ssr = S01 - S10;
            float r = sqrtf(cc*cc + ssr*ssr);
            cc /= r; ssr /= r;
            float tx = qbx - (cc*qax - ssr*qay);
            float ty = qby - (ssr*qax + cc*qay);

            const float* pt = pos_trans + bb2*9;
            float trx = pt[2], tryy = pt[5];
            float r00 = pt[0], r01 = pt[1], r10 = pt[3], r11 = pt[4];
            float lt = sqrtf((trx - tx)*(trx - tx) + (tryy - ty)*(tryy - ty));
            float q00 = r00*cc - r01*ssr;
            float q01 = r00*ssr + r01*cc;
            float q10 = r10*cc - r11*ssr;
            float q11 = r10*ssr + r11*cc;
            float lR = sqrtf((q00-1.f)*(q00-1.f) + q01*q01 + q10*q10 + (q11-1.f)*(q11-1.f));
            losses[bb2] = lt + 10.0f * lR;
        }
        __syncthreads();
        if (t == 0)
            out[0] = 0.25f * (losses[0] + losses[1] + losses[2] + losses[3]);
    }
}

// ---------------- launcher ----------------
extern "C" void kernel_launch(void* const* d_in, const int* in_sizes, int n_in,
                              void* d_out, int out_size)
{
    const float* loc1  = (const float*)d_in[0];
    const float* sc1   = (const float*)d_in[1];
    const float* desc1 = (const float*)d_in[2];
    const float* sc2   = (const float*)d_in[3];
    const float* desc2 = (const float*)d_in[4];
    const float* pos   = (const float*)d_in[5];
    float* out = (float*)d_out;

    static int smem_set = 0;
    if (!smem_set) {
        cudaFuncSetAttribute(mma_kernel, cudaFuncAttributeMaxDynamicSharedMemorySize, SM_TOTAL);
        smem_set = 1;
    }

    prep_kernel<<<KPB + D2NB, 128>>>(loc1, desc1, sc1, desc2);
    mma_kernel<<<dim3(MT, Bq), 256, SM_TOTAL>>>();
    reduce_dd_kernel<<<dim3(NK, Bq), 256>>>(desc2, sc2, pos, out);
}

// round 13
// speedup vs baseline: 1.0019x; 1.0019x over previous
#include <cuda_runtime.h>
#include <cuda_bf16.h>
#include <math.h>
#include <stdint.h>

#define Bq   4
#define Cc   128
#define Hh   240
#define Ww   240
#define NK   400
#define CELL 12
#define GHW  20
#define PATCH 144
#define HWIMG (Hh*Ww)     /* 57600 */
#define MT   450          /* m-tiles of 128 */
#define EPSV 1e-6f

// ---------------- scratch (static device globals; no allocation) ----------------
__device__ float g_ps[Bq*NK*2];
__device__ float g_pd[Bq*NK*2];
__device__ float g_ds[Bq*NK*Cc];
__device__ __nv_bfloat16 g_ds_bf16[Bq*NK*Cc];
__device__ __nv_bfloat16 g_d2n[(size_t)Bq*Cc*HWIMG];   // 59 MB normalized desc2
__device__ float g_ss[Bq*NK];
__device__ float g_w[Bq*NK];
__device__ float4 g_part[(size_t)Bq*NK*MT];   // 11.5 MB, [b][row][mt]
__device__ unsigned int g_cnt;                // zero-init; reset by last block each run

// ================= helpers =================
__device__ __forceinline__ uint32_t smem_u32(const void* p) {
    uint32_t a;
    asm("{ .reg .u64 t; cvta.to.shared.u64 t, %1; cvt.u32.u64 %0, t; }" : "=r"(a) : "l"(p));
    return a;
}
__device__ __forceinline__ void ldmat4(uint32_t* r, uint32_t addr) {
    asm volatile("ldmatrix.sync.aligned.m8n8.x4.shared.b16 {%0,%1,%2,%3}, [%4];"
        : "=r"(r[0]), "=r"(r[1]), "=r"(r[2]), "=r"(r[3]) : "r"(addr));
}
__device__ __forceinline__ void ldmat4t(uint32_t* r, uint32_t addr) {
    asm volatile("ldmatrix.sync.aligned.m8n8.x4.trans.shared.b16 {%0,%1,%2,%3}, [%4];"
        : "=r"(r[0]), "=r"(r[1]), "=r"(r[2]), "=r"(r[3]) : "r"(addr));
}
__device__ __forceinline__ void mma16816(float* c, const uint32_t* a, const uint32_t* b) {
    asm volatile("mma.sync.aligned.m16n8k16.row.col.f32.bf16.bf16.f32 "
        "{%0,%1,%2,%3}, {%4,%5,%6,%7}, {%8,%9}, {%0,%1,%2,%3};"
        : "+f"(c[0]), "+f"(c[1]), "+f"(c[2]), "+f"(c[3])
        : "r"(a[0]), "r"(a[1]), "r"(a[2]), "r"(a[3]), "r"(b[0]), "r"(b[1]));
}
#define CP16(dst, src)  asm volatile("cp.async.cg.shared.global [%0], [%1], 16;" :: "r"(dst), "l"(src))
#define CP_COMMIT()     asm volatile("cp.async.commit_group;")
#define CP_WAIT(n)      asm volatile("cp.async.wait_group %0;" :: "n"(n))

// swizzled byte offset within a [rows x 128 bf16] tile (row pitch 256B)
#define SWZ(row, c16) ((uint32_t)(row)*256u + (uint32_t)(((c16) ^ ((row)&7)) << 4))

// block reductions over 128 threads (broadcast to all)
__device__ __forceinline__ float block_sum_128(float v, float* red4)
{
    #pragma unroll
    for (int o = 16; o > 0; o >>= 1) v += __shfl_xor_sync(0xffffffffu, v, o);
    int w = threadIdx.x >> 5;
    __syncthreads();
    if ((threadIdx.x & 31) == 0) red4[w] = v;
    __syncthreads();
    return red4[0] + red4[1] + red4[2] + red4[3];
}
__device__ __forceinline__ float block_max_128(float v, float* red4)
{
    #pragma unroll
    for (int o = 16; o > 0; o >>= 1) v = fmaxf(v, __shfl_xor_sync(0xffffffffu, v, o));
    int w = threadIdx.x >> 5;
    __syncthreads();
    if ((threadIdx.x & 31) == 0) red4[w] = v;
    __syncthreads();
    return fmaxf(fmaxf(red4[0], red4[1]), fmaxf(red4[2], red4[3]));
}
// fused 3-value reduction over 256 threads (8 warps), ONE barrier
__device__ __forceinline__ void block_sum3_256(float& a, float& b, float& c, float* red24)
{
    #pragma unroll
    for (int o = 16; o > 0; o >>= 1) {
        a += __shfl_xor_sync(0xffffffffu, a, o);
        b += __shfl_xor_sync(0xffffffffu, b, o);
        c += __shfl_xor_sync(0xffffffffu, c, o);
    }
    int w = threadIdx.x >> 5;
    if ((threadIdx.x & 31) == 0) { red24[w*3] = a; red24[w*3+1] = b; red24[w*3+2] = c; }
    __syncthreads();
    a = red24[0]; b = red24[1]; c = red24[2];
    #pragma unroll
    for (int i = 1; i < 8; i++) { a += red24[i*3]; b += red24[i*3+1]; c += red24[i*3+2]; }
}

// bilinear helpers ---------------------------------------------------------
__device__ __forceinline__ void bilin_setup(float px, float py,
    int& x0, int& y0, int& x1, int& y1, float& wx, float& wy)
{
    float x = fminf(fmaxf(px, 0.f), (float)(Ww-1));
    float y = fminf(fmaxf(py, 0.f), (float)(Hh-1));
    float x0f = floorf(x), y0f = floorf(y);
    wx = x - x0f; wy = y - y0f;
    x0 = (int)x0f; y0 = (int)y0f;
    x1 = min(x0 + 1, Ww-1);
    y1 = min(y0 + 1, Hh-1);
}
__device__ __forceinline__ float bilin_fetch(const float* __restrict__ base,
    int x0, int y0, int x1, int y1, float wx, float wy)
{
    float v00 = base[y0*Ww + x0];
    float v01 = base[y0*Ww + x1];
    float v10 = base[y1*Ww + x0];
    float v11 = base[y1*Ww + x1];
    return v00*(1.f-wx)*(1.f-wy) + v01*wx*(1.f-wy) + v10*(1.f-wx)*wy + v11*wx*wy;
}

// ---------------- 1) fused prep: keypoints+ds OR desc2-normalize (role by blockIdx) ----
#define KPB   (NK*Bq)            /* 1600 kpds blocks */
#define D2NB  ((Bq*Cc*Hh)/4)     /* 30720 d2n blocks (4 warps = 4 rows each) */

__global__ void prep_kernel(const float* __restrict__ loc,
                            const float* __restrict__ desc1,
                            const float* __restrict__ sc1,
                            const float* __restrict__ desc2)
{
    int blk = blockIdx.x;
    int t = threadIdx.x;   // 128

    if (blk >= KPB) {
        // ---- d2n role: one warp per (b,c,y) row ----
        int gwarp = (blk - KPB)*4 + (t >> 5);
        int lane  = t & 31;
        const float* rowp = desc2 + (size_t)gwarp * Ww;
        float v[8];
        float s = 0.f;
        #pragma unroll
        for (int k = 0; k < 8; k++) {
            int x = lane + k*32;
            v[k] = (x < Ww) ? rowp[x] : 0.f;
            s += v[k]*v[k];
        }
        #pragma unroll
        for (int o = 16; o > 0; o >>= 1) s += __shfl_xor_sync(0xffffffffu, s, o);
        float inv = 1.f / (sqrtf(s) + EPSV);
        __nv_bfloat16* outp = g_d2n + (size_t)gwarp * Ww;
        #pragma unroll
        for (int k = 0; k < 8; k++) {
            int x = lane + k*32;
            if (x < Ww) outp[x] = __float2bfloat16(v[k] * inv);
        }
        return;
    }

    // ---- kpds role ----
    int n = blk % NK, b = blk / NK;
    int i = n / GHW, j = n % GHW;
    __shared__ float red4[4];

    int r0 = t / CELL, c0 = t % CELL;
    float v0 = loc[((size_t)b*Hh + i*CELL + r0)*Ww + j*CELL + c0];
    float v1 = -1e30f; int r1 = 0, c1 = 0;
    if (t < PATCH - 128) {
        int e = t + 128;
        r1 = e / CELL; c1 = e % CELL;
        v1 = loc[((size_t)b*Hh + i*CELL + r1)*Ww + j*CELL + c1];
    }
    float mx = block_max_128(fmaxf(v0, v1), red4);
    float p0 = __expf(v0 - mx);
    float p1 = (t < PATCH - 128) ? __expf(v1 - mx) : 0.f;

    float s  = block_sum_128(p0 + p1, red4);
    float sx = block_sum_128(p0*(float)c0 + p1*(float)c1, red4);
    float sy = block_sum_128(p0*(float)r0 + p1*(float)r1, red4);

    float psx = sx / s + (float)(i * CELL);   // reference quirk: x offset from ROW block
    float psy = sy / s + (float)(j * CELL);
    if (t == 0) {
        g_ps[(b*NK + n)*2 + 0] = psx;
        g_ps[(b*NK + n)*2 + 1] = psy;
    }

    int c = t;
    int x0,y0,x1,y1; float wx,wy;
    bilin_setup(psx, psy, x0,y0,x1,y1, wx,wy);

    const float* base = desc1 + ((size_t)b*Cc + c) * HWIMG;
    float v = bilin_fetch(base, x0,y0,x1,y1, wx,wy);

    float tot = block_sum_128(v*v, red4);
    float nrm = sqrtf(tot) + EPSV;
    float dsv = v / nrm;
    g_ds[((size_t)b*NK + n)*Cc + c] = dsv;
    g_ds_bf16[((size_t)b*NK + n)*Cc + c] = __float2bfloat16(dsv);

    if (c == 0) {
        const float* sb = sc1 + (size_t)b*HWIMG;
        g_ss[b*NK + n] = bilin_fetch(sb, x0,y0,x1,y1, wx,wy);
    }
}

// ---------------- 2) fused HMMA GEMM + partial softmax (round-11 structure) ----------
// grid (MT, Bq), 256 threads (8 warps, 4x2; warp tile 32n x 64m).
#define SM_A0    0
#define SM_A1    32768
#define SM_BS    65536
#define SM_STAT  98304                 /* float[3][128] = 1536 B */
#define SM_TOTAL 99840

__global__ void __launch_bounds__(256, 2)
mma_kernel()
{
    extern __shared__ char smem[];
    uint32_t sbase = smem_u32(smem);
    float* statS = (float*)(smem + SM_STAT);
    float* statY = statS + 128;
    float* statX = statS + 256;
    int tid  = threadIdx.x;
    int lane = tid & 31;
    int wid  = tid >> 5;
    int wr   = wid >> 1;        // warp row 0..3
    int wc   = wid & 1;         // warp col 0..1
    int mt   = blockIdx.x, b = blockIdx.y;
    int m0   = mt * 128;

    const char* abase = (const char*)(g_ds_bf16 + (size_t)b*NK*Cc);
    const char* bbase = (const char*)(g_d2n + (size_t)b*Cc*HWIMG);

    // prefetch B (g0)
    #pragma unroll
    for (int k = 0; k < 8; k++) {
        int gi  = tid + k*256;
        int c   = gi >> 4;
        int c16 = gi & 15;
        CP16(sbase + SM_BS + SWZ(c, c16),
             bbase + ((size_t)c*HWIMG + m0)*2 + c16*16);
    }
    CP_COMMIT();
    // prefetch A0 (g1), A1 (g2)
    #pragma unroll
    for (int at = 0; at < 2; at++) {
        const char* asrc = abase + (size_t)at*128*256;
        uint32_t dbase = sbase + (at ? SM_A1 : SM_A0);
        #pragma unroll
        for (int k = 0; k < 8; k++) {
            int gi  = tid + k*256;
            int row = gi >> 4;
            int c16 = gi & 15;
            CP16(dbase + SWZ(row, c16), asrc + (size_t)gi*16);
        }
        CP_COMMIT();
    }

    uint32_t bs_base = sbase + SM_BS;

    int arow  = wr*32 + (lane & 15);
    int ako   = lane >> 4;
    int bcrow = (lane & 7) + (((lane >> 3) & 1) << 3);
    int bmsub = (lane >> 4) << 3;

    #pragma unroll
    for (int at = 0; at < 3; at++) {
        CP_WAIT(1);
        __syncthreads();

        uint32_t as_base = sbase + ((at & 1) ? SM_A1 : SM_A0);

        float acc[2][8][4];
        #pragma unroll
        for (int mi = 0; mi < 2; mi++)
            #pragma unroll
            for (int nf = 0; nf < 8; nf++)
                #pragma unroll
                for (int q = 0; q < 4; q++) acc[mi][nf][q] = 0.f;

        #pragma unroll
        for (int ks = 0; ks < 8; ks++) {
            uint32_t a0[4], a1[4];
            ldmat4(a0, as_base + SWZ(arow,      ks*2 + ako));
            ldmat4(a1, as_base + SWZ(arow + 16, ks*2 + ako));
            uint32_t bfr[4][4];
            #pragma unroll
            for (int np = 0; np < 4; np++)
                ldmat4t(bfr[np], bs_base + SWZ(ks*16 + bcrow, (wc*64 + np*16 + bmsub) >> 3));
            #pragma unroll
            for (int nf = 0; nf < 8; nf++) {
                uint32_t bb[2];
                bb[0] = bfr[nf >> 1][(nf & 1)*2 + 0];
                bb[1] = bfr[nf >> 1][(nf & 1)*2 + 1];
                mma16816(acc[0][nf], a0, bb);
                mma16816(acc[1][nf], a1, bb);
            }
        }

        __syncthreads();   // all warps done reading this A buf

        // refill BEFORE epilogue so DMA overlaps exp/store
        if (at == 0) {
            const char* asrc = abase + (size_t)2*128*256;   // A2 -> buf0
            #pragma unroll
            for (int k = 0; k < 8; k++) {
                int gi  = tid + k*256;
                int row = gi >> 4;
                int c16 = gi & 15;
                CP16(sbase + SM_A0 + SWZ(row, c16), asrc + (size_t)gi*16);
            }
            CP_COMMIT();
        } else if (at == 1) {
            const char* asrc = abase + (size_t)384*256;     // tail -> buf1
            int row = tid >> 4;
            int c16 = tid & 15;
            CP16(sbase + SM_A1 + SWZ(row, c16), asrc + (size_t)tid*16);
            CP_COMMIT();
        }

        // epilogue: exp + coord sums; combine wc halves via smem
        float st[2][2][3];
        #pragma unroll
        for (int mi = 0; mi < 2; mi++) {
            float s0=0.f, sy0=0.f, sx0=0.f, s1=0.f, sy1=0.f, sx1=0.f;
            #pragma unroll
            for (int nf = 0; nf < 8; nf++) {
                int col = wc*64 + nf*8 + (lane & 3)*2;
                int m   = m0 + col;
                int ya  = m / Ww;        float yaf = (float)ya, xaf = (float)(m - ya*Ww);
                int mb2 = m + 1;
                int yb  = mb2 / Ww;      float ybf = (float)yb, xbf = (float)(mb2 - yb*Ww);
                float e;
                e = __expf(acc[mi][nf][0]); s0 += e; sy0 += e*yaf; sx0 += e*xaf;
                e = __expf(acc[mi][nf][1]); s0 += e; sy0 += e*ybf; sx0 += e*xbf;
                e = __expf(acc[mi][nf][2]); s1 += e; sy1 += e*yaf; sx1 += e*xaf;
                e = __expf(acc[mi][nf][3]); s1 += e; sy1 += e*ybf; sx1 += e*xbf;
            }
            #pragma unroll
            for (int o = 1; o <= 2; o <<= 1) {
                s0  += __shfl_xor_sync(0xffffffffu, s0,  o);
                sy0 += __shfl_xor_sync(0xffffffffu, sy0, o);
                sx0 += __shfl_xor_sync(0xffffffffu, sx0, o);
                s1  += __shfl_xor_sync(0xffffffffu, s1,  o);
                sy1 += __shfl_xor_sync(0xffffffffu, sy1, o);
                sx1 += __shfl_xor_sync(0xffffffffu, sx1, o);
            }
            st[mi][0][0]=s0; st[mi][0][1]=sy0; st[mi][0][2]=sx0;
            st[mi][1][0]=s1; st[mi][1][1]=sy1; st[mi][1][2]=sx1;
        }
        if (wc == 1 && (lane & 3) == 0) {
            #pragma unroll
            for (int mi = 0; mi < 2; mi++) {
                int rl = wr*32 + mi*16 + (lane >> 2);
                statS[rl]   = st[mi][0][0]; statY[rl]   = st[mi][0][1]; statX[rl]   = st[mi][0][2];
                statS[rl+8] = st[mi][1][0]; statY[rl+8] = st[mi][1][1]; statX[rl+8] = st[mi][1][2];
            }
        }
        __syncthreads();
        if (wc == 0 && (lane & 3) == 0) {
            #pragma unroll
            for (int mi = 0; mi < 2; mi++) {
                int rl = wr*32 + mi*16 + (lane >> 2);
                g_part[((size_t)b*NK + at*128 + rl)*MT + mt] =
                    make_float4(st[mi][0][0]+statS[rl], st[mi][0][1]+statY[rl], st[mi][0][2]+statX[rl], 0.f);
                g_part[((size_t)b*NK + at*128 + rl + 8)*MT + mt] =
                    make_float4(st[mi][1][0]+statS[rl+8], st[mi][1][1]+statY[rl+8], st[mi][1][2]+statX[rl+8], 0.f);
            }
        }
    }

    // ---- tail tile: rows 384..399 (16 rows), warps 0,1 only ----
    CP_WAIT(0);
    __syncthreads();
    float tst[2][3];
    if (wid < 2) {
        uint32_t as_base = sbase + SM_A1;
        float acc[8][4];
        #pragma unroll
        for (int nf = 0; nf < 8; nf++)
            #pragma unroll
            for (int q = 0; q < 4; q++) acc[nf][q] = 0.f;

        int arow_t = lane & 15;
        #pragma unroll
        for (int ks = 0; ks < 8; ks++) {
            uint32_t a[4];
            ldmat4(a, as_base + SWZ(arow_t, ks*2 + ako));
            uint32_t bfr[4][4];
            #pragma unroll
            for (int np = 0; np < 4; np++)
                ldmat4t(bfr[np], bs_base + SWZ(ks*16 + bcrow, (wc*64 + np*16 + bmsub) >> 3));
            #pragma unroll
            for (int nf = 0; nf < 8; nf++) {
                uint32_t bb[2];
                bb[0] = bfr[nf >> 1][(nf & 1)*2 + 0];
                bb[1] = bfr[nf >> 1][(nf & 1)*2 + 1];
                mma16816(acc[nf], a, bb);
            }
        }

        float s0=0.f, sy0=0.f, sx0=0.f, s1=0.f, sy1=0.f, sx1=0.f;
        #pragma unroll
        for (int nf = 0; nf < 8; nf++) {
            int col = wc*64 + nf*8 + (lane & 3)*2;
            int m   = m0 + col;
            int ya  = m / Ww;        float yaf = (float)ya, xaf = (float)(m - ya*Ww);
            int mb2 = m + 1;
            int yb  = mb2 / Ww;      float ybf = (float)yb, xbf = (float)(mb2 - yb*Ww);
            float e;
            e = __expf(acc[nf][0]); s0 += e; sy0 += e*yaf; sx0 += e*xaf;
            e = __expf(acc[nf][1]); s0 += e; sy0 += e*ybf; sx0 += e*xbf;
            e = __expf(acc[nf][2]); s1 += e; sy1 += e*yaf; sx1 += e*xaf;
            e = __expf(acc[nf][3]); s1 += e; sy1 += e*ybf; sx1 += e*xbf;
        }
        #pragma unroll
        for (int o = 1; o <= 2; o <<= 1) {
            s0  += __shfl_xor_sync(0xffffffffu, s0,  o);
            sy0 += __shfl_xor_sync(0xffffffffu, sy0, o);
            sx0 += __shfl_xor_sync(0xffffffffu, sx0, o);
            s1  += __shfl_xor_sync(0xffffffffu, s1,  o);
            sy1 += __shfl_xor_sync(0xffffffffu, sy1, o);
            sx1 += __shfl_xor_sync(0xffffffffu, sx1, o);
        }
        tst[0][0]=s0; tst[0][1]=sy0; tst[0][2]=sx0;
        tst[1][0]=s1; tst[1][1]=sy1; tst[1][2]=sx1;
        if (wid == 1 && (lane & 3) == 0) {
            int rl = lane >> 2;
            statS[rl]   = s0; statY[rl]   = sy0; statX[rl]   = sx0;
            statS[rl+8] = s1; statY[rl+8] = sy1; statX[rl+8] = sx1;
        }
    }
    __syncthreads();
    if (wid == 0 && (lane & 3) == 0) {
        int rl = lane >> 2;
        g_part[((size_t)b*NK + 384 + rl)*MT + mt] =
            make_float4(tst[0][0]+statS[rl], tst[0][1]+statY[rl], tst[0][2]+statX[rl], 0.f);
        g_part[((size_t)b*NK + 384 + rl + 8)*MT + mt] =
            make_float4(tst[1][0]+statS[rl+8], tst[1][1]+statY[rl+8], tst[1][2]+statX[rl+8], 0.f);
    }
}

// ---------------- 3) fused reduce -> pd -> dd + w_ -> (last block) pose + loss ----------
__global__ void reduce_dd_kernel(const float* __restrict__ desc2, const float* __restrict__ sc2,
                                 const float* __restrict__ pos_trans, float* __restrict__ out)
{
    int n = blockIdx.x, b = blockIdx.y;
    int t = threadIdx.x;  // 256
    __shared__ float red24[24];
    __shared__ float pd_s[2];
    __shared__ unsigned int lastFlag;

    // --- reduce partials (coalesced, fused 3-value reduction) ---
    {
        const float4* src = g_part + ((size_t)b*NK + n)*MT;
        float4 p0 = (t       < MT) ? src[t]       : make_float4(0,0,0,0);
        float4 p1 = (t + 256 < MT) ? src[t + 256] : make_float4(0,0,0,0);
        float s  = p0.x + p1.x;
        float sy = p0.y + p1.y;
        float sx = p0.z + p1.z;
        block_sum3_256(s, sy, sx, red24);
        if (t == 0) {
            float v0 = sy / s, v1 = sx / s;
            pd_s[0] = v0; pd_s[1] = v1;
            g_pd[(b*NK+n)*2 + 0] = v0;
            g_pd[(b*NK+n)*2 + 1] = v1;
        }
        __syncthreads();
    }

    // --- dd: bilinear(desc2, pd), normalize, dot with ds; sd; w_ ---
    float px = pd_s[0];   // pd[...,0] consumed as "x" (reference quirk)
    float py = pd_s[1];
    int x0,y0,x1,y1; float wx,wy;
    bilin_setup(px, py, x0,y0,x1,y1, wx,wy);

    float v = 0.f, dsv = 0.f;
    if (t < Cc) {
        const float* base = desc2 + ((size_t)b*Cc + t) * HWIMG;
        v = bilin_fetch(base, x0,y0,x1,y1, wx,wy);
        dsv = g_ds[((size_t)b*NK + n)*Cc + t];
    }
    float ssq = v*v, sdot = dsv*v, dummy = 0.f;
    __syncthreads();   // red24 reuse safety
    block_sum3_256(ssq, sdot, dummy, red24);

    if (t == 0) {
        float dot = sdot / (sqrtf(ssq) + EPSV);
        const float* sb = sc2 + (size_t)b*HWIMG;
        float sd = bilin_fetch(sb, x0,y0,x1,y1, wx,wy);
        g_w[b*NK + n] = (dot + 1.f) * (g_ss[b*NK + n] * sd) * 0.5f;
        __threadfence();
        unsigned int vcnt = atomicAdd(&g_cnt, 1u);
        lastFlag = (vcnt == (unsigned int)(NK*Bq - 1)) ? 1u : 0u;
    }
    __syncthreads();
    if (!lastFlag) return;

    // ===== last block: pose estimation + loss + mean (all g_w/g_pd now visible) =====
    if (t == 0) g_cnt = 0;    // reset for next graph replay

    __shared__ float sp[8][9];
    __shared__ float losses[Bq];
    {
        int wid = t >> 5, lane = t & 31;
        int bb = wid & 3;          // batch
        int half = wid >> 2;       // two warps per batch
        const float RES = 0.25f;
        const float OX = (Ww - 1) * 0.5f;
        const float OY = (Hh - 1) * 0.5f;

        float W=0, Ax=0, Ay=0, Bx=0, By=0, M00=0, M01=0, M10=0, M11=0;
        for (int k = lane + half*32; k < NK; k += 64) {
            float wv = g_w[bb*NK + k];
            float psx = g_ps[(bb*NK+k)*2+0], psy = g_ps[(bb*NK+k)*2+1];
            float pdx = g_pd[(bb*NK+k)*2+0], pdy = g_pd[(bb*NK+k)*2+1];
            float qsx = (psx - OX) * RES, qsy = (OY - psy) * RES;
            float qdx = (pdx - OX) * RES, qdy = (OY - pdy) * RES;
            W  += wv;
            Ax += wv*qsx; Ay += wv*qsy;
            Bx += wv*qdx; By += wv*qdy;
            M00 += wv*qsx*qdx; M01 += wv*qsx*qdy;
            M10 += wv*qsy*qdx; M11 += wv*qsy*qdy;
        }
        #pragma unroll
        for (int o = 16; o > 0; o >>= 1) {
            W   += __shfl_xor_sync(0xffffffffu, W,   o);
            Ax  += __shfl_xor_sync(0xffffffffu, Ax,  o);
            Ay  += __shfl_xor_sync(0xffffffffu, Ay,  o);
            Bx  += __shfl_xor_sync(0xffffffffu, Bx,  o);
            By  += __shfl_xor_sync(0xffffffffu, By,  o);
            M00 += __shfl_xor_sync(0xffffffffu, M00, o);
            M01 += __shfl_xor_sync(0xffffffffu, M01, o);
            M10 += __shfl_xor_sync(0xffffffffu, M10, o);
            M11 += __shfl_xor_sync(0xffffffffu, M11, o);
        }
        if (lane == 0) {
            sp[wid][0]=W;  sp[wid][1]=Ax;  sp[wid][2]=Ay;
            sp[wid][3]=Bx; sp[wid][4]=By;  sp[wid][5]=M00;
            sp[wid][6]=M01; sp[wid][7]=M10; sp[wid][8]=M11;
        }
        __syncthreads();
        if (t < Bq) {
            int bb2 = t;
            float Wc   = sp[bb2][0] + sp[bb2+4][0];
            float Axc  = sp[bb2][1] + sp[bb2+4][1];
            float Ayc  = sp[bb2][2] + sp[bb2+4][2];
            float Bxc  = sp[bb2][3] + sp[bb2+4][3];
            float Byc  = sp[bb2][4] + sp[bb2+4][4];
            float m00  = sp[bb2][5] + sp[bb2+4][5];
            float m01  = sp[bb2][6] + sp[bb2+4][6];
            float m10  = sp[bb2][7] + sp[bb2+4][7];
            float m11  = sp[bb2][8] + sp[bb2+4][8];
            float wsum = Wc + EPSV;
            float qax = Axc / wsum, qay = Ayc / wsum;
            float qbx = Bxc / wsum, qby = Byc / wsum;
            float S00 = m00 - qax*Bxc - Axc*qbx + Wc*qax*qbx;
            float S01 = m01 - qax*Byc - Axc*qby + Wc*qax*qby;
            float S10 = m10 - qay*Bxc - Ayc*qbx + Wc*qay*qbx;
            float S11 = m11 - qay*Byc - Ayc*qby + Wc*qay*qby;
            float cc = S00 + S11;
            float ssr = S01 - S10;
            float r = sqrtf(cc*cc + ssr*ssr);
            cc /= r; ssr /= r;
            float tx = qbx - (cc*qax - ssr*qay);
            float ty = qby - (ssr*qax + cc*qay);

            const float* pt = pos_trans + bb2*9;
            float trx = pt[2], tryy = pt[5];
            float r00 = pt[0], r01 = pt[1], r10 = pt[3], r11 = pt[4];
            float lt = sqrtf((trx - tx)*(trx - tx) + (tryy - ty)*(tryy - ty));
            float q00 = r00*cc - r01*ssr;
            float q01 = r00*ssr + r01*cc;
            float q10 = r10*cc - r11*ssr;
            float q11 = r10*ssr + r11*cc;
            float lR = sqrtf((q00-1.f)*(q00-1.f) + q01*q01 + q10*q10 + (q11-1.f)*(q11-1.f));
            losses[bb2] = lt + 10.0f * lR;
        }
        __syncthreads();
        if (t == 0)
            out[0] = 0.25f * (losses[0] + losses[1] + losses[2] + losses[3]);
    }
}

// ---------------- launcher ----------------
extern "C" void kernel_launch(void* const* d_in, const int* in_sizes, int n_in,
                              void* d_out, int out_size)
{
    const float* loc1  = (const float*)d_in[0];
    const float* sc1   = (const float*)d_in[1];
    const float* desc1 = (const float*)d_in[2];
    const float* sc2   = (const float*)d_in[3];
    const float* desc2 = (const float*)d_in[4];
    const float* pos   = (const float*)d_in[5];
    float* out = (float*)d_out;

    static int smem_set = 0;
    if (!smem_set) {
        cudaFuncSetAttribute(mma_kernel, cudaFuncAttributeMaxDynamicSharedMemorySize, SM_TOTAL);
        smem_set = 1;
    }

    prep_kernel<<<KPB + D2NB, 128>>>(loc1, desc1, sc1, desc2);
    mma_kernel<<<dim3(MT, Bq), 256, SM_TOTAL>>>();
    reduce_dd_kernel<<<dim3(NK, Bq), 256>>>(desc2, sc2, pos, out);
}

// round 14
// speedup vs baseline: 1.0499x; 1.0478x over previous
#include <cuda_runtime.h>
#include <cuda_bf16.h>
#include <math.h>
#include <stdint.h>

#define Bq   4
#define Cc   128
#define Hh   240
#define Ww   240
#define NK   400
#define CELL 12
#define GHW  20
#define PATCH 144
#define HWIMG (Hh*Ww)     /* 57600 */
#define MT   450          /* m-tiles of 128 */
#define EPSV 1e-6f
#define LOG2E 1.44269504088896f

// ---------------- scratch (static device globals; no allocation) ----------------
__device__ float g_ps[Bq*NK*2];
__device__ float g_pd[Bq*NK*2];
__device__ float g_ds[Bq*NK*Cc];
__device__ __nv_bfloat16 g_ds_bf16[Bq*NK*Cc];
__device__ __nv_bfloat16 g_d2n[(size_t)Bq*Cc*HWIMG];   // 59 MB normalized desc2 (x log2e)
__device__ float g_ss[Bq*NK];
__device__ float g_w[Bq*NK];
__device__ float4 g_part[(size_t)Bq*NK*MT];   // 11.5 MB, [b][row][mt]

// ================= helpers =================
__device__ __forceinline__ uint32_t smem_u32(const void* p) {
    uint32_t a;
    asm("{ .reg .u64 t; cvta.to.shared.u64 t, %1; cvt.u32.u64 %0, t; }" : "=r"(a) : "l"(p));
    return a;
}
__device__ __forceinline__ float ex2(float x) {
    float r; asm("ex2.approx.f32 %0, %1;" : "=f"(r) : "f"(x)); return r;
}
__device__ __forceinline__ void ldmat4(uint32_t* r, uint32_t addr) {
    asm volatile("ldmatrix.sync.aligned.m8n8.x4.shared.b16 {%0,%1,%2,%3}, [%4];"
        : "=r"(r[0]), "=r"(r[1]), "=r"(r[2]), "=r"(r[3]) : "r"(addr));
}
__device__ __forceinline__ void ldmat4t(uint32_t* r, uint32_t addr) {
    asm volatile("ldmatrix.sync.aligned.m8n8.x4.trans.shared.b16 {%0,%1,%2,%3}, [%4];"
        : "=r"(r[0]), "=r"(r[1]), "=r"(r[2]), "=r"(r[3]) : "r"(addr));
}
__device__ __forceinline__ void mma16816(float* c, const uint32_t* a, const uint32_t* b) {
    asm volatile("mma.sync.aligned.m16n8k16.row.col.f32.bf16.bf16.f32 "
        "{%0,%1,%2,%3}, {%4,%5,%6,%7}, {%8,%9}, {%0,%1,%2,%3};"
        : "+f"(c[0]), "+f"(c[1]), "+f"(c[2]), "+f"(c[3])
        : "r"(a[0]), "r"(a[1]), "r"(a[2]), "r"(a[3]), "r"(b[0]), "r"(b[1]));
}
#define CP16(dst, src)  asm volatile("cp.async.cg.shared.global [%0], [%1], 16;" :: "r"(dst), "l"(src))
#define CP_COMMIT()     asm volatile("cp.async.commit_group;")
#define CP_WAIT(n)      asm volatile("cp.async.wait_group %0;" :: "n"(n))

// swizzled byte offset within a [rows x 128 bf16] tile (row pitch 256B)
#define SWZ(row, c16) ((uint32_t)(row)*256u + (uint32_t)(((c16) ^ ((row)&7)) << 4))

// block reductions over 128 threads (broadcast to all)
__device__ __forceinline__ float block_sum_128(float v, float* red4)
{
    #pragma unroll
    for (int o = 16; o > 0; o >>= 1) v += __shfl_xor_sync(0xffffffffu, v, o);
    int w = threadIdx.x >> 5;
    __syncthreads();
    if ((threadIdx.x & 31) == 0) red4[w] = v;
    __syncthreads();
    return red4[0] + red4[1] + red4[2] + red4[3];
}
__device__ __forceinline__ float block_max_128(float v, float* red4)
{
    #pragma unroll
    for (int o = 16; o > 0; o >>= 1) v = fmaxf(v, __shfl_xor_sync(0xffffffffu, v, o));
    int w = threadIdx.x >> 5;
    __syncthreads();
    if ((threadIdx.x & 31) == 0) red4[w] = v;
    __syncthreads();
    return fmaxf(fmaxf(red4[0], red4[1]), fmaxf(red4[2], red4[3]));
}
// fused 3-value reduction over 256 threads (8 warps), ONE barrier
__device__ __forceinline__ void block_sum3_256(float& a, float& b, float& c, float* red24)
{
    #pragma unroll
    for (int o = 16; o > 0; o >>= 1) {
        a += __shfl_xor_sync(0xffffffffu, a, o);
        b += __shfl_xor_sync(0xffffffffu, b, o);
        c += __shfl_xor_sync(0xffffffffu, c, o);
    }
    int w = threadIdx.x >> 5;
    if ((threadIdx.x & 31) == 0) { red24[w*3] = a; red24[w*3+1] = b; red24[w*3+2] = c; }
    __syncthreads();
    a = red24[0]; b = red24[1]; c = red24[2];
    #pragma unroll
    for (int i = 1; i < 8; i++) { a += red24[i*3]; b += red24[i*3+1]; c += red24[i*3+2]; }
}

// bilinear helpers ---------------------------------------------------------
__device__ __forceinline__ void bilin_setup(float px, float py,
    int& x0, int& y0, int& x1, int& y1, float& wx, float& wy)
{
    float x = fminf(fmaxf(px, 0.f), (float)(Ww-1));
    float y = fminf(fmaxf(py, 0.f), (float)(Hh-1));
    float x0f = floorf(x), y0f = floorf(y);
    wx = x - x0f; wy = y - y0f;
    x0 = (int)x0f; y0 = (int)y0f;
    x1 = min(x0 + 1, Ww-1);
    y1 = min(y0 + 1, Hh-1);
}
__device__ __forceinline__ float bilin_fetch(const float* __restrict__ base,
    int x0, int y0, int x1, int y1, float wx, float wy)
{
    float v00 = base[y0*Ww + x0];
    float v01 = base[y0*Ww + x1];
    float v10 = base[y1*Ww + x0];
    float v11 = base[y1*Ww + x1];
    return v00*(1.f-wx)*(1.f-wy) + v01*wx*(1.f-wy) + v10*(1.f-wx)*wy + v11*wx*wy;
}

// ---------------- 1) fused prep: keypoints+ds OR desc2-normalize (role by blockIdx) ----
#define KPB   (NK*Bq)            /* 1600 kpds blocks */
#define D2NB  ((Bq*Cc*Hh)/4)     /* 30720 d2n blocks (4 warps = 4 rows each) */

__global__ void prep_kernel(const float* __restrict__ loc,
                            const float* __restrict__ desc1,
                            const float* __restrict__ sc1,
                            const float* __restrict__ desc2)
{
    int blk = blockIdx.x;
    int t = threadIdx.x;   // 128

    if (blk >= KPB) {
        // ---- d2n role: one warp per (b,c,y) row; float2 loads, bf16x2 stores ----
        int gwarp = (blk - KPB)*4 + (t >> 5);
        int lane  = t & 31;
        const float2* rowp = (const float2*)(desc2 + (size_t)gwarp * Ww);  // 120 float2
        float2 v[4];
        float s = 0.f;
        #pragma unroll
        for (int k = 0; k < 4; k++) {
            int idx = lane + k*32;
            if (idx < 120) v[k] = rowp[idx]; else v[k] = make_float2(0.f, 0.f);
            s += v[k].x*v[k].x + v[k].y*v[k].y;
        }
        #pragma unroll
        for (int o = 16; o > 0; o >>= 1) s += __shfl_xor_sync(0xffffffffu, s, o);
        // fold log2(e) into the normalization so the GEMM epilogue can use ex2
        float inv = LOG2E / (sqrtf(s) + EPSV);
        uint32_t* outp = (uint32_t*)(g_d2n + (size_t)gwarp * Ww);
        #pragma unroll
        for (int k = 0; k < 4; k++) {
            int idx = lane + k*32;
            if (idx < 120) {
                __nv_bfloat162 p = __floats2bfloat162_rn(v[k].x * inv, v[k].y * inv);
                outp[idx] = *(uint32_t*)&p;
            }
        }
        return;
    }

    // ---- kpds role ----
    int n = blk % NK, b = blk / NK;
    int i = n / GHW, j = n % GHW;
    __shared__ float red4[4];

    int r0 = t / CELL, c0 = t % CELL;
    float v0 = loc[((size_t)b*Hh + i*CELL + r0)*Ww + j*CELL + c0];
    float v1 = -1e30f; int r1 = 0, c1 = 0;
    if (t < PATCH - 128) {
        int e = t + 128;
        r1 = e / CELL; c1 = e % CELL;
        v1 = loc[((size_t)b*Hh + i*CELL + r1)*Ww + j*CELL + c1];
    }
    float mx = block_max_128(fmaxf(v0, v1), red4);
    float p0 = __expf(v0 - mx);
    float p1 = (t < PATCH - 128) ? __expf(v1 - mx) : 0.f;

    float s  = block_sum_128(p0 + p1, red4);
    float sx = block_sum_128(p0*(float)c0 + p1*(float)c1, red4);
    float sy = block_sum_128(p0*(float)r0 + p1*(float)r1, red4);

    float psx = sx / s + (float)(i * CELL);   // reference quirk: x offset from ROW block
    float psy = sy / s + (float)(j * CELL);
    if (t == 0) {
        g_ps[(b*NK + n)*2 + 0] = psx;
        g_ps[(b*NK + n)*2 + 1] = psy;
    }

    int c = t;
    int x0,y0,x1,y1; float wx,wy;
    bilin_setup(psx, psy, x0,y0,x1,y1, wx,wy);

    const float* base = desc1 + ((size_t)b*Cc + c) * HWIMG;
    float v = bilin_fetch(base, x0,y0,x1,y1, wx,wy);

    float tot = block_sum_128(v*v, red4);
    float nrm = sqrtf(tot) + EPSV;
    float dsv = v / nrm;
    g_ds[((size_t)b*NK + n)*Cc + c] = dsv;
    g_ds_bf16[((size_t)b*NK + n)*Cc + c] = __float2bfloat16(dsv);

    if (c == 0) {
        const float* sb = sc1 + (size_t)b*HWIMG;
        g_ss[b*NK + n] = bilin_fetch(sb, x0,y0,x1,y1, wx,wy);
    }
}

// ---------------- 2) fused HMMA GEMM + partial softmax (round-11 structure) ----------
// grid (MT, Bq), 256 threads (8 warps, 4x2; warp tile 32n x 64m).
#define SM_A0    0
#define SM_A1    32768
#define SM_BS    65536
#define SM_STAT  98304                 /* float[3][128] = 1536 B */
#define SM_TOTAL 99840

__global__ void __launch_bounds__(256, 2)
mma_kernel()
{
    extern __shared__ char smem[];
    uint32_t sbase = smem_u32(smem);
    float* statS = (float*)(smem + SM_STAT);
    float* statY = statS + 128;
    float* statX = statS + 256;
    int tid  = threadIdx.x;
    int lane = tid & 31;
    int wid  = tid >> 5;
    int wr   = wid >> 1;        // warp row 0..3
    int wc   = wid & 1;         // warp col 0..1
    int mt   = blockIdx.x, b = blockIdx.y;
    int m0   = mt * 128;

    const char* abase = (const char*)(g_ds_bf16 + (size_t)b*NK*Cc);
    const char* bbase = (const char*)(g_d2n + (size_t)b*Cc*HWIMG);

    // prefetch B (g0)
    #pragma unroll
    for (int k = 0; k < 8; k++) {
        int gi  = tid + k*256;
        int c   = gi >> 4;
        int c16 = gi & 15;
        CP16(sbase + SM_BS + SWZ(c, c16),
             bbase + ((size_t)c*HWIMG + m0)*2 + c16*16);
    }
    CP_COMMIT();
    // prefetch A0 (g1), A1 (g2)
    #pragma unroll
    for (int at = 0; at < 2; at++) {
        const char* asrc = abase + (size_t)at*128*256;
        uint32_t dbase = sbase + (at ? SM_A1 : SM_A0);
        #pragma unroll
        for (int k = 0; k < 8; k++) {
            int gi  = tid + k*256;
            int row = gi >> 4;
            int c16 = gi & 15;
            CP16(dbase + SWZ(row, c16), asrc + (size_t)gi*16);
        }
        CP_COMMIT();
    }

    uint32_t bs_base = sbase + SM_BS;

    int arow  = wr*32 + (lane & 15);
    int ako   = lane >> 4;
    int bcrow = (lane & 7) + (((lane >> 3) & 1) << 3);
    int bmsub = (lane >> 4) << 3;

    #pragma unroll
    for (int at = 0; at < 3; at++) {
        CP_WAIT(1);
        __syncthreads();

        uint32_t as_base = sbase + ((at & 1) ? SM_A1 : SM_A0);

        float acc[2][8][4];
        #pragma unroll
        for (int mi = 0; mi < 2; mi++)
            #pragma unroll
            for (int nf = 0; nf < 8; nf++)
                #pragma unroll
                for (int q = 0; q < 4; q++) acc[mi][nf][q] = 0.f;

        #pragma unroll
        for (int ks = 0; ks < 8; ks++) {
            uint32_t a0[4], a1[4];
            ldmat4(a0, as_base + SWZ(arow,      ks*2 + ako));
            ldmat4(a1, as_base + SWZ(arow + 16, ks*2 + ako));
            uint32_t bfr[4][4];
            #pragma unroll
            for (int np = 0; np < 4; np++)
                ldmat4t(bfr[np], bs_base + SWZ(ks*16 + bcrow, (wc*64 + np*16 + bmsub) >> 3));
            #pragma unroll
            for (int nf = 0; nf < 8; nf++) {
                uint32_t bb[2];
                bb[0] = bfr[nf >> 1][(nf & 1)*2 + 0];
                bb[1] = bfr[nf >> 1][(nf & 1)*2 + 1];
                mma16816(acc[0][nf], a0, bb);
                mma16816(acc[1][nf], a1, bb);
            }
        }

        __syncthreads();   // all warps done reading this A buf

        // refill BEFORE epilogue so DMA overlaps exp/store
        if (at == 0) {
            const char* asrc = abase + (size_t)2*128*256;   // A2 -> buf0
            #pragma unroll
            for (int k = 0; k < 8; k++) {
                int gi  = tid + k*256;
                int row = gi >> 4;
                int c16 = gi & 15;
                CP16(sbase + SM_A0 + SWZ(row, c16), asrc + (size_t)gi*16);
            }
            CP_COMMIT();
        } else if (at == 1) {
            const char* asrc = abase + (size_t)384*256;     // tail -> buf1
            int row = tid >> 4;
            int c16 = tid & 15;
            CP16(sbase + SM_A1 + SWZ(row, c16), asrc + (size_t)tid*16);
            CP_COMMIT();
        }

        // epilogue: ex2 + coord sums (acc already scaled by log2e; |acc|<=16.3)
        float st[2][2][3];
        #pragma unroll
        for (int mi = 0; mi < 2; mi++) {
            float s0=0.f, sy0=0.f, sx0=0.f, s1=0.f, sy1=0.f, sx1=0.f;
            #pragma unroll
            for (int nf = 0; nf < 8; nf++) {
                int col = wc*64 + nf*8 + (lane & 3)*2;
                int m   = m0 + col;
                int ya  = m / Ww;        float yaf = (float)ya, xaf = (float)(m - ya*Ww);
                int mb2 = m + 1;
                int yb  = mb2 / Ww;      float ybf = (float)yb, xbf = (float)(mb2 - yb*Ww);
                float e;
                e = ex2(acc[mi][nf][0]); s0 += e; sy0 += e*yaf; sx0 += e*xaf;
                e = ex2(acc[mi][nf][1]); s0 += e; sy0 += e*ybf; sx0 += e*xbf;
                e = ex2(acc[mi][nf][2]); s1 += e; sy1 += e*yaf; sx1 += e*xaf;
                e = ex2(acc[mi][nf][3]); s1 += e; sy1 += e*ybf; sx1 += e*xbf;
            }
            #pragma unroll
            for (int o = 1; o <= 2; o <<= 1) {
                s0  += __shfl_xor_sync(0xffffffffu, s0,  o);
                sy0 += __shfl_xor_sync(0xffffffffu, sy0, o);
                sx0 += __shfl_xor_sync(0xffffffffu, sx0, o);
                s1  += __shfl_xor_sync(0xffffffffu, s1,  o);
                sy1 += __shfl_xor_sync(0xffffffffu, sy1, o);
                sx1 += __shfl_xor_sync(0xffffffffu, sx1, o);
            }
            st[mi][0][0]=s0; st[mi][0][1]=sy0; st[mi][0][2]=sx0;
            st[mi][1][0]=s1; st[mi][1][1]=sy1; st[mi][1][2]=sx1;
        }
        if (wc == 1 && (lane & 3) == 0) {
            #pragma unroll
            for (int mi = 0; mi < 2; mi++) {
                int rl = wr*32 + mi*16 + (lane >> 2);
                statS[rl]   = st[mi][0][0]; statY[rl]   = st[mi][0][1]; statX[rl]   = st[mi][0][2];
                statS[rl+8] = st[mi][1][0]; statY[rl+8] = st[mi][1][1]; statX[rl+8] = st[mi][1][2];
            }
        }
        __syncthreads();
        if (wc == 0 && (lane & 3) == 0) {
            #pragma unroll
            for (int mi = 0; mi < 2; mi++) {
                int rl = wr*32 + mi*16 + (lane >> 2);
                g_part[((size_t)b*NK + at*128 + rl)*MT + mt] =
                    make_float4(st[mi][0][0]+statS[rl], st[mi][0][1]+statY[rl], st[mi][0][2]+statX[rl], 0.f);
                g_part[((size_t)b*NK + at*128 + rl + 8)*MT + mt] =
                    make_float4(st[mi][1][0]+statS[rl+8], st[mi][1][1]+statY[rl+8], st[mi][1][2]+statX[rl+8], 0.f);
            }
        }
    }

    // ---- tail tile: rows 384..399 (16 rows), warps 0,1 only ----
    CP_WAIT(0);
    __syncthreads();
    float tst[2][3];
    if (wid < 2) {
        uint32_t as_base = sbase + SM_A1;
        float acc[8][4];
        #pragma unroll
        for (int nf = 0; nf < 8; nf++)
            #pragma unroll
            for (int q = 0; q < 4; q++) acc[nf][q] = 0.f;

        int arow_t = lane & 15;
        #pragma unroll
        for (int ks = 0; ks < 8; ks++) {
            uint32_t a[4];
            ldmat4(a, as_base + SWZ(arow_t, ks*2 + ako));
            uint32_t bfr[4][4];
            #pragma unroll
            for (int np = 0; np < 4; np++)
                ldmat4t(bfr[np], bs_base + SWZ(ks*16 + bcrow, (wc*64 + np*16 + bmsub) >> 3));
            #pragma unroll
            for (int nf = 0; nf < 8; nf++) {
                uint32_t bb[2];
                bb[0] = bfr[nf >> 1][(nf & 1)*2 + 0];
                bb[1] = bfr[nf >> 1][(nf & 1)*2 + 1];
                mma16816(acc[nf], a, bb);
            }
        }

        float s0=0.f, sy0=0.f, sx0=0.f, s1=0.f, sy1=0.f, sx1=0.f;
        #pragma unroll
        for (int nf = 0; nf < 8; nf++) {
            int col = wc*64 + nf*8 + (lane & 3)*2;
            int m   = m0 + col;
            int ya  = m / Ww;        float yaf = (float)ya, xaf = (float)(m - ya*Ww);
            int mb2 = m + 1;
            int yb  = mb2 / Ww;      float ybf = (float)yb, xbf = (float)(mb2 - yb*Ww);
            float e;
            e = ex2(acc[nf][0]); s0 += e; sy0 += e*yaf; sx0 += e*xaf;
            e = ex2(acc[nf][1]); s0 += e; sy0 += e*ybf; sx0 += e*xbf;
            e = ex2(acc[nf][2]); s1 += e; sy1 += e*yaf; sx1 += e*xaf;
            e = ex2(acc[nf][3]); s1 += e; sy1 += e*ybf; sx1 += e*xbf;
        }
        #pragma unroll
        for (int o = 1; o <= 2; o <<= 1) {
            s0  += __shfl_xor_sync(0xffffffffu, s0,  o);
            sy0 += __shfl_xor_sync(0xffffffffu, sy0, o);
            sx0 += __shfl_xor_sync(0xffffffffu, sx0, o);
            s1  += __shfl_xor_sync(0xffffffffu, s1,  o);
            sy1 += __shfl_xor_sync(0xffffffffu, sy1, o);
            sx1 += __shfl_xor_sync(0xffffffffu, sx1, o);
        }
        tst[0][0]=s0; tst[0][1]=sy0; tst[0][2]=sx0;
        tst[1][0]=s1; tst[1][1]=sy1; tst[1][2]=sx1;
        if (wid == 1 && (lane & 3) == 0) {
            int rl = lane >> 2;
            statS[rl]   = s0; statY[rl]   = sy0; statX[rl]   = sx0;
            statS[rl+8] = s1; statY[rl+8] = sy1; statX[rl+8] = sx1;
        }
    }
    __syncthreads();
    if (wid == 0 && (lane & 3) == 0) {
        int rl = lane >> 2;
        g_part[((size_t)b*NK + 384 + rl)*MT + mt] =
            make_float4(tst[0][0]+statS[rl], tst[0][1]+statY[rl], tst[0][2]+statX[rl], 0.f);
        g_part[((size_t)b*NK + 384 + rl + 8)*MT + mt] =
            make_float4(tst[1][0]+statS[rl+8], tst[1][1]+statY[rl+8], tst[1][2]+statX[rl+8], 0.f);
    }
}

// ---------------- 3) fused reduce -> pd -> dd + sd + w_ (256 threads) ----------------
__global__ void reduce_dd_kernel(const float* __restrict__ desc2, const float* __restrict__ sc2)
{
    int n = blockIdx.x, b = blockIdx.y;
    int t = threadIdx.x;  // 256
    __shared__ float red24[24];
    __shared__ float pd_s[2];

    // --- reduce partials (coalesced, fused 3-value reduction) ---
    {
        const float4* src = g_part + ((size_t)b*NK + n)*MT;
        float4 p0 = (t       < MT) ? src[t]       : make_float4(0,0,0,0);
        float4 p1 = (t + 256 < MT) ? src[t + 256] : make_float4(0,0,0,0);
        float s  = p0.x + p1.x;
        float sy = p0.y + p1.y;
        float sx = p0.z + p1.z;
        block_sum3_256(s, sy, sx, red24);
        if (t == 0) {
            float v0 = sy / s, v1 = sx / s;
            pd_s[0] = v0; pd_s[1] = v1;
            g_pd[(b*NK+n)*2 + 0] = v0;
            g_pd[(b*NK+n)*2 + 1] = v1;
        }
        __syncthreads();
    }

    // --- dd: bilinear(desc2, pd), normalize, dot with ds; sd; w_ ---
    float px = pd_s[0];   // pd[...,0] consumed as "x" (reference quirk)
    float py = pd_s[1];
    int x0,y0,x1,y1; float wx,wy;
    bilin_setup(px, py, x0,y0,x1,y1, wx,wy);

    float v = 0.f, dsv = 0.f;
    if (t < Cc) {
        const float* base = desc2 + ((size_t)b*Cc + t) * HWIMG;
        v = bilin_fetch(base, x0,y0,x1,y1, wx,wy);
        dsv = g_ds[((size_t)b*NK + n)*Cc + t];
    }
    float ssq = v*v, sdot = dsv*v, dummy = 0.f;
    __syncthreads();   // red24 reuse safety
    block_sum3_256(ssq, sdot, dummy, red24);

    if (t == 0) {
        float dot = sdot / (sqrtf(ssq) + EPSV);
        const float* sb = sc2 + (size_t)b*HWIMG;
        float sd = bilin_fetch(sb, x0,y0,x1,y1, wx,wy);
        g_w[b*NK + n] = (dot + 1.f) * (g_ss[b*NK + n] * sd) * 0.5f;
    }
}

// ---------------- 4) pose + loss + mean: smem-staged, warp-per-batch ----------------
__global__ void pose_final_kernel(const float* __restrict__ pos_trans, float* __restrict__ out)
{
    __shared__ float sw[Bq*NK];        // 6.4 KB
    __shared__ float sps[Bq*NK*2];     // 12.8 KB
    __shared__ float spd[Bq*NK*2];     // 12.8 KB
    __shared__ float losses[Bq];

    int t = threadIdx.x;               // 128
    {
        const float4* w4  = (const float4*)g_w;
        const float4* ps4 = (const float4*)g_ps;
        const float4* pd4 = (const float4*)g_pd;
        float4* dw  = (float4*)sw;
        float4* dps = (float4*)sps;
        float4* dpd = (float4*)spd;
        #pragma unroll
        for (int k = 0; k < 4; k++) {
            int i = t + k*128;
            if (i < Bq*NK/4) dw[i] = w4[i];
        }
        #pragma unroll
        for (int k = 0; k < 7; k++) {
            int i = t + k*128;
            if (i < Bq*NK/2) { dps[i] = ps4[i]; dpd[i] = pd4[i]; }
        }
    }
    __syncthreads();

    int b = t >> 5;
    int lane = t & 31;
    const float RES = 0.25f;
    const float OX = (Ww - 1) * 0.5f;
    const float OY = (Hh - 1) * 0.5f;

    float W=0, Ax=0, Ay=0, Bx=0, By=0, M00=0, M01=0, M10=0, M11=0;
    for (int n = lane; n < NK; n += 32) {
        float wv = sw[b*NK + n];
        float psx = sps[(b*NK+n)*2+0], psy = sps[(b*NK+n)*2+1];
        float pdx = spd[(b*NK+n)*2+0], pdy = spd[(b*NK+n)*2+1];
        float qsx = (psx - OX) * RES, qsy = (OY - psy) * RES;
        float qdx = (pdx - OX) * RES, qdy = (OY - pdy) * RES;
        W  += wv;
        Ax += wv*qsx; Ay += wv*qsy;
        Bx += wv*qdx; By += wv*qdy;
        M00 += wv*qsx*qdx; M01 += wv*qsx*qdy;
        M10 += wv*qsy*qdx; M11 += wv*qsy*qdy;
    }
    #pragma unroll
    for (int o = 16; o > 0; o >>= 1) {
        W   += __shfl_xor_sync(0xffffffffu, W,   o);
        Ax  += __shfl_xor_sync(0xffffffffu, Ax,  o);
        Ay  += __shfl_xor_sync(0xffffffffu, Ay,  o);
        Bx  += __shfl_xor_sync(0xffffffffu, Bx,  o);
        By  += __shfl_xor_sync(0xffffffffu, By,  o);
        M00 += __shfl_xor_sync(0xffffffffu, M00, o);
        M01 += __shfl_xor_sync(0xffffffffu, M01, o);
        M10 += __shfl_xor_sync(0xffffffffu, M10, o);
        M11 += __shfl_xor_sync(0xffffffffu, M11, o);
    }
    if (lane == 0) {
        float wsum = W + EPSV;
        float qax = Ax / wsum, qay = Ay / wsum;
        float qbx = Bx / wsum, qby = By / wsum;
        float S00 = M00 - qax*Bx - Ax*qbx + W*qax*qbx;
        float S01 = M01 - qax*By - Ax*qby + W*qax*qby;
        float S10 = M10 - qay*Bx - Ay*qbx + W*qay*qbx;
        float S11 = M11 - qay*By - Ay*qby + W*qay*qby;
        float cc = S00 + S11;
        float ss = S01 - S10;
        float r = sqrtf(cc*cc + ss*ss);
        cc /= r; ss /= r;
        float tx = qbx - (cc*qax - ss*qay);
        float ty = qby - (ss*qax + cc*qay);

        const float* pt = pos_trans + b*9;
        float trx = pt[2], tryy = pt[5];
        float r00 = pt[0], r01 = pt[1], r10 = pt[3], r11 = pt[4];
        float lt = sqrtf((trx - tx)*(trx - tx) + (tryy - ty)*(tryy - ty));
        float q00 = r00*cc - r01*ss;
        float q01 = r00*ss + r01*cc;
        float q10 = r10*cc - r11*ss;
        float q11 = r10*ss + r11*cc;
        float lR = sqrtf((q00-1.f)*(q00-1.f) + q01*q01 + q10*q10 + (q11-1.f)*(q11-1.f));
        losses[b] = lt + 10.0f * lR;
    }
    __syncthreads();
    if (t == 0)
        out[0] = 0.25f * (losses[0] + losses[1] + losses[2] + losses[3]);
}

// ---------------- launcher ----------------
extern "C" void kernel_launch(void* const* d_in, const int* in_sizes, int n_in,
                              void* d_out, int out_size)
{
    const float* loc1  = (const float*)d_in[0];
    const float* sc1   = (const float*)d_in[1];
    const float* desc1 = (const float*)d_in[2];
    const float* sc2   = (const float*)d_in[3];
    const float* desc2 = (const float*)d_in[4];
    const float* pos   = (const float*)d_in[5];
    float* out = (float*)d_out;

    static int smem_set = 0;
    if (!smem_set) {
        cudaFuncSetAttribute(mma_kernel, cudaFuncAttributeMaxDynamicSharedMemorySize, SM_TOTAL);
        smem_set = 1;
    }

    prep_kernel<<<KPB + D2NB, 128>>>(loc1, desc1, sc1, desc2);
    mma_kernel<<<dim3(MT, Bq), 256, SM_TOTAL>>>();
    reduce_dd_kernel<<<dim3(NK, Bq), 256>>>(desc2, sc2);
    pose_final_kernel<<<1, 128>>>(pos, out);
}